// round 14
// baseline (speedup 1.0000x reference)
#include <cuda_runtime.h>
#include <cuda_fp16.h>
#include <math.h>

#define BATCH 64
#define SEQ   512
#define DIN   128
#define HID   512
#define OUTN  24
#define K0    640
#define K1    1024
#define COLS  2048

#define NCTA   128
#define NBG    4
#define NCTABG 32
#define NT     256

// fp16 weight words (u32 = half2) per old-style column-group of 8 units
#define WPW_L0 10240               // 40 k16-blocks * 4 n8-blocks * 64 words
#define WPW_L1 16384               // 64 * 4 * 64
#define WPW    (WPW_L0 + WPW_L1)   // 26624 u32 per cg

#define AS_STRIDE 260              // 256 words (512 fp16) + 4 pad
#define AS_WORDS (16 * AS_STRIDE)  // 4160

// red: 2 layers x 4 kq x [16][68] floats
#define RED_PER   1088
#define RED_FLOATS (8 * RED_PER)

#define SMEM_U32  (2 * AS_WORDS + RED_FLOATS + 64 + 16)
#define SMEM_BYTES (SMEM_U32 * 4)

#define XG_SMEM_U32 (128 * 68 + 16384)
#define XG_SMEM_BYTES (XG_SMEM_U32 * 4)

// fc1: w tile [32][516] floats + h tile [16][256] half2 words
#define FC1_SMEM_U32 (32 * 516 + 4096)
#define FC1_SMEM_BYTES (FC1_SMEM_U32 * 4)

// ---------------- persistent device state ----------------------------------
__device__ __align__(16) unsigned d_Wp[64 * WPW];
__device__ __align__(16) unsigned d_x16[BATCH * SEQ * (DIN / 2)];
__device__ __align__(16) unsigned d_xz[BATCH * SEQ * (COLS / 2)];
__device__ float d_b0r[COLS];
__device__ float d_b1r[COLS];
__device__ __align__(16) unsigned d_h0[2][BATCH * (HID / 2)];
__device__ __align__(16) unsigned d_h1[2][BATCH * (HID / 2)];
__device__ float d_y1[BATCH * HID];
// Two fused barrier words per bg (each on own 128B line):
//   bar0 (h0-ready) at bg*64, bar1 (h1-ready) at bg*64+32.
// Word: low16 = arrivals, high16 = round (monotonic, replay-safe).
__device__ unsigned g_bar[NBG * 64];

__device__ __forceinline__ float sigf(float v) { return 1.0f / (1.0f + __expf(-v)); }
__device__ __forceinline__ float tanha(float v) {
    float r; asm("tanh.approx.f32 %0, %1;" : "=f"(r) : "f"(v)); return r;
}

__device__ __forceinline__ void mma16(float c[4], unsigned a0, unsigned a1,
                                      unsigned a2, unsigned a3,
                                      unsigned b0, unsigned b1)
{
    asm volatile(
        "mma.sync.aligned.m16n8k16.row.col.f32.f16.f16.f32 "
        "{%0,%1,%2,%3},{%4,%5,%6,%7},{%8,%9},{%0,%1,%2,%3};"
        : "+f"(c[0]), "+f"(c[1]), "+f"(c[2]), "+f"(c[3])
        : "r"(a0), "r"(a1), "r"(a2), "r"(a3), "r"(b0), "r"(b1));
}

__device__ __forceinline__ void ldsm4(unsigned& a0, unsigned& a1,
                                      unsigned& a2, unsigned& a3, unsigned addr)
{
    asm volatile(
        "ldmatrix.sync.aligned.m8n8.x4.shared.b16 {%0,%1,%2,%3}, [%4];"
        : "=r"(a0), "=r"(a1), "=r"(a2), "=r"(a3) : "r"(addr));
}

__device__ __forceinline__ void cpa16(void* dst, const void* src)
{
    unsigned d = (unsigned)__cvta_generic_to_shared(dst);
    asm volatile("cp.async.cg.shared.global [%0], [%1], 16;" :: "r"(d), "l"(src));
}
__device__ __forceinline__ void cpa_commit()
{
    asm volatile("cp.async.commit_group;");
}
template<int N>
__device__ __forceinline__ void cpa_wait()
{
    asm volatile("cp.async.wait_group %0;" :: "n"(N));
}
__device__ __forceinline__ void pair_bar(int id)
{
    asm volatile("bar.sync %0, 64;" :: "r"(id) : "memory");
}

// ---------------- prep: weight packing (fp16), x conversion, biases ---------
__global__ void prep_kernel(
    const float* __restrict__ x,
    const float* __restrict__ wf0, const float* __restrict__ wi0,
    const float* __restrict__ wo0, const float* __restrict__ wg0,
    const float* __restrict__ bf0, const float* __restrict__ bi0,
    const float* __restrict__ bo0, const float* __restrict__ bg0,
    const float* __restrict__ wf1, const float* __restrict__ wi1,
    const float* __restrict__ wo1, const float* __restrict__ wg1,
    const float* __restrict__ bf1, const float* __restrict__ bi1,
    const float* __restrict__ bo1, const float* __restrict__ bg1)
{
    const int nW = 64 * WPW;
    const int nX = BATCH * SEQ * (DIN / 2);
    const int ntot = nW + nX + 2 * COLS;
    for (int idx = blockIdx.x * blockDim.x + threadIdx.x; idx < ntot;
         idx += gridDim.x * blockDim.x) {
        if (idx < nW) {
            int cg = idx / WPW;
            int r  = idx % WPW;
            int layer = (r < WPW_L0) ? 0 : 1;
            int rr    = layer ? (r - WPW_L0) : r;
            int kb   = rr >> 8;
            int rem  = rr & 255;
            int nb   = rem >> 6;
            int t    = rem & 63;
            int lane = t >> 1;
            int reg  = t & 1;
            int colloc = nb * 8 + (lane >> 2);
            int unit = cg * 8 + (colloc >> 2);
            int gate = colloc & 3;
            int k    = kb * 16 + (lane & 3) * 2 + reg * 8;
            const float* w;
            int K;
            if (layer == 0) {
                w = (gate == 0) ? wf0 : (gate == 1) ? wi0 : (gate == 2) ? wo0 : wg0;
                K = K0;
            } else {
                w = (gate == 0) ? wf1 : (gate == 1) ? wi1 : (gate == 2) ? wo1 : wg1;
                K = K1;
            }
            __half2 h2 = __floats2half2_rn(w[unit * K + k], w[unit * K + k + 1]);
            d_Wp[idx] = *(unsigned*)&h2;
        } else if (idx < nW + nX) {
            int i = idx - nW;
            __half2 h2 = __floats2half2_rn(x[2 * i], x[2 * i + 1]);
            d_x16[i] = *(unsigned*)&h2;
        } else {
            int col = idx - nW - nX;
            if (col < COLS) {
                int u = col >> 2, g = col & 3;
                const float* bb = (g == 0) ? bf0 : (g == 1) ? bi0 : (g == 2) ? bo0 : bg0;
                d_b0r[col] = bb[u];
            } else {
                col -= COLS;
                int u = col >> 2, g = col & 3;
                const float* bb = (g == 0) ? bf1 : (g == 1) ? bi1 : (g == 2) ? bo1 : bg1;
                d_b1r[col] = bb[u];
            }
        }
    }
}

// ---------------- xz GEMM: xz[b,t,:] = x_t @ Wx0^T + b0 (fp16 out) ----------
__global__ void __launch_bounds__(NT) xz_gemm_kernel()
{
    extern __shared__ unsigned smem_u[];
    unsigned* As = smem_u;                 // [128][68]
    unsigned* Ws = smem_u + 128 * 68;      // 8 cgs * 2048 words

    const int tid  = threadIdx.x;
    const int w    = tid >> 5, lane = tid & 31;
    const int r4   = lane >> 2, kq4 = lane & 3;
    const int row0 = blockIdx.x * 128;
    const int cg0  = blockIdx.y * 8;

    #pragma unroll
    for (int i = tid; i < 2048; i += NT) {
        int row = i >> 4, w4 = (i & 15) * 4;
        cpa16(As + row * 68 + w4, d_x16 + (size_t)(row0 + row) * 64 + w4);
    }
    #pragma unroll
    for (int i = tid; i < 4096; i += NT) {
        int cgL = i >> 9, r = (i & 511) * 4;
        cpa16(Ws + cgL * 2048 + r, d_Wp + (size_t)(cg0 + cgL) * WPW + r);
    }
    cpa_commit();
    cpa_wait<0>();
    __syncthreads();

    float acc[32][4];
    #pragma unroll
    for (int i = 0; i < 32; ++i)
        { acc[i][0] = 0.f; acc[i][1] = 0.f; acc[i][2] = 0.f; acc[i][3] = 0.f; }

    #pragma unroll
    for (int kb = 0; kb < 8; ++kb) {
        const unsigned* ab = As + (w * 16 + r4) * 68 + kb * 8 + kq4;
        unsigned a0 = ab[0];
        unsigned a1 = ab[8 * 68];
        unsigned a2 = ab[4];
        unsigned a3 = ab[8 * 68 + 4];
        #pragma unroll
        for (int j = 0; j < 32; ++j) {
            const unsigned* bp = Ws + (j >> 2) * 2048 + kb * 256 + (j & 3) * 64 + lane * 2;
            uint2 b = *(const uint2*)bp;
            mma16(acc[j], a0, a1, a2, a3, b.x, b.y);
        }
    }

    #pragma unroll
    for (int j = 0; j < 32; ++j) {
        int col = (cg0 + (j >> 2)) * 32 + (j & 3) * 8 + 2 * (lane & 3);
        float bs0 = d_b0r[col], bs1 = d_b0r[col + 1];
        int mrow = row0 + w * 16 + r4;
        __half2 p0 = __floats2half2_rn(acc[j][0] + bs0, acc[j][1] + bs1);
        __half2 p1 = __floats2half2_rn(acc[j][2] + bs0, acc[j][3] + bs1);
        d_xz[(size_t)mrow * 1024 + (col >> 1)]        = *(unsigned*)&p0;
        d_xz[(size_t)(mrow + 8) * 1024 + (col >> 1)]  = *(unsigned*)&p1;
    }
}

// ---------------- fused single-word barrier (release/acquire) -----------------
// off = word offset into g_bar. Arrive: syncthreads (CTA stores visible) then
// tid0 release-add (blessed CG grid-sync pattern).
__device__ __forceinline__ void bar_arrive(int off)
{
    __syncthreads();
    if (threadIdx.x == 0) {
        unsigned prev;
        asm volatile("atom.release.gpu.global.add.u32 %0, [%1], %2;"
                     : "=r"(prev) : "l"(&g_bar[off]), "r"(1u) : "memory");
        if ((prev & 0xFFFFu) == NCTABG - 1) {
            unsigned d;
            asm volatile("atom.release.gpu.global.add.u32 %0, [%1], %2;"
                         : "=r"(d) : "l"(&g_bar[off]),
                           "r"(0x10000u - NCTABG) : "memory");
        }
    }
}
// ALL threads poll with acquire loads and resume independently.
__device__ __forceinline__ void bar_wait(int off, unsigned base, unsigned mygen)
{
    const unsigned* p = &g_bar[off];
    unsigned v;
    do {
        asm volatile("ld.acquire.gpu.global.u32 %0, [%1];"
                     : "=r"(v) : "l"(p) : "memory");
    } while ((((v >> 16) - base) & 0xFFFFu) < mygen);
}

// ---------------- persistent scan kernel --------------------------------------
// 128 CTAs = 4 batch-groups (16 batches) x 32 unit-groups (16 units = 64 cols)
// warps: 4 K-quarters (kq) x 2 col-halves (wn). L1 K-split is kq-interleaved.
// Split barriers: bar0 = h0-ready (critical L0 loop), bar1 = h1-ready.
__global__ void __launch_bounds__(NT, 1) scan_kernel()
{
    extern __shared__ unsigned smem_u[];
    unsigned* As0   = smem_u;                    // [16][260]  h0[t]
    unsigned* As1   = As0 + AS_WORDS;            // [16][260]  h1[t-1]
    float*    red   = (float*)(As1 + AS_WORDS);  // [2 layers][4 kq][16][68]
    float*    bias1 = red + RED_FLOATS;          // [64]

    const int tid  = threadIdx.x;
    const int cg   = blockIdx.x & 31;
    const int bg   = blockIdx.x >> 5;
    const int w    = tid >> 5, lane = tid & 31;
    const int wn   = w & 1;                      // col half (32 cols)
    const int kq   = w >> 1;                     // K quarter
    const int r4   = lane >> 2;

    const int fb = tid >> 4, fu = tid & 15;

    const int off0 = bg * 64;
    const int off1 = bg * 64 + 32;

    // Snapshot rounds BEFORE this CTA's first arrives (replay-safe).
    unsigned base0 = (*(volatile unsigned*)&g_bar[off0]) >> 16;
    unsigned base1 = (*(volatile unsigned*)&g_bar[off1]) >> 16;

    // ---- one-time: B fragments -> registers ----
    const int cgA = cg * 2 + wn;
    uint2 B0[8][4];       // L0 recurrent: blocks kq*8+j
    uint2 B1a[8][4];      // L1 h0-part:   blocks kq*8+j
    uint2 B1b[8][4];      // L1 h1-part:   blocks 32+kq*8+j
    {
        const unsigned* w0 = d_Wp + (size_t)cgA * WPW + 2048
                           + (kq * 8) * 256 + lane * 2;
        #pragma unroll
        for (int j = 0; j < 8; ++j)
            #pragma unroll
            for (int n = 0; n < 4; ++n)
                B0[j][n] = *(const uint2*)(w0 + j * 256 + n * 64);
        const unsigned* w1 = d_Wp + (size_t)cgA * WPW + WPW_L0
                           + (kq * 8) * 256 + lane * 2;
        #pragma unroll
        for (int j = 0; j < 8; ++j)
            #pragma unroll
            for (int n = 0; n < 4; ++n)
                B1a[j][n] = *(const uint2*)(w1 + j * 256 + n * 64);
        const unsigned* w1b = w1 + 32 * 256;
        #pragma unroll
        for (int j = 0; j < 8; ++j)
            #pragma unroll
            for (int n = 0; n < 4; ++n)
                B1b[j][n] = *(const uint2*)(w1b + j * 256 + n * 64);
    }
    if (tid < 64) bias1[tid] = d_b1r[cg * 64 + tid];

    // zero this bg's t=-1 hidden rows
    {
        int idx = cg * NT + tid;
        if (idx < 4096) d_h0[1][bg * 4096 + idx] = 0u;
        else            d_h1[1][bg * 4096 + (idx - 4096)] = 0u;
    }
    float c0 = 0.0f, c1 = 0.0f;
    bar_arrive(off0);
    bar_arrive(off1);
    unsigned mygen = 1;

    // ldmatrix per-lane addresses (blocks kq*8+j live in quarter kq)
    unsigned smem_base = (unsigned)__cvta_generic_to_shared(smem_u);
    const int lrow = lane & 15;
    const int lcol = (lane >> 4) * 4;
    const unsigned la0  = smem_base + (unsigned)(lrow * AS_STRIDE + lcol) * 4;
    const unsigned la1h = la0 + AS_WORDS * 4;    // same pattern in As1

    float* red0 = red + kq * RED_PER;
    float* red1 = red + 4 * RED_PER + kq * RED_PER;
    const int barid = 1 + kq;

    for (int k = 0; k <= SEQ; ++k) {
        const int doL0 = (k < SEQ);
        const int doL1 = (k >= 1);

        // xz prefetch (no dependency on h) — overlap with barrier propagation
        uint2 zraw;
        if (doL0)
            zraw = *(const uint2*)(d_xz +
                    (size_t)((bg * 16 + fb) * SEQ + k) * 1024 + cg * 32 + fu * 2);

        // ===== critical path: wait h0-ready, stage As0 immediately ============
        bar_wait(off0, base0, mygen);
        {
            const unsigned* __restrict__ h0prev = d_h0[(k + 1) & 1];
            #pragma unroll
            for (int it = 0; it < 4; ++it) {
                int idx = it * 32 + lane;            // 0..127
                int row = wn * 8 + (idx >> 4);
                int wd  = kq * 64 + (idx & 15) * 4;
                cpa16(As0 + row * AS_STRIDE + wd,
                      h0prev + (bg * 16 + row) * 256 + wd);
            }
        }
        cpa_commit();
        if (doL1) {
            bar_wait(off1, base1, mygen);
            const unsigned* __restrict__ h1prev = d_h1[k & 1];
            #pragma unroll
            for (int it = 0; it < 4; ++it) {
                int idx = it * 32 + lane;
                int row = wn * 8 + (idx >> 4);
                int wd  = kq * 64 + (idx & 15) * 4;
                cpa16(As1 + row * AS_STRIDE + wd,
                      h1prev + (bg * 16 + row) * 256 + wd);
            }
        }
        cpa_commit();                    // always commit (possibly empty group)
        ++mygen;

        cpa_wait<1>();                   // own As0 quarter done
        pair_bar(barid);                 // partner's half of the quarter done

        const int cbb = 2 * (lane & 3);

        // ===== fused pass over As0: L0 MMA + L1 h0-part MMA share fragments ===
        float acc0[4][4] = {};
        float acc1[4][4] = {};
        #pragma unroll
        for (int j = 0; j < 8; ++j) {
            unsigned a0, a1, a2, a3;
            ldsm4(a0, a1, a2, a3, la0 + (unsigned)(kq * 8 + j) * 32);
            if (doL0) {
                #pragma unroll
                for (int n = 0; n < 4; ++n)
                    mma16(acc0[n], a0, a1, a2, a3, B0[j][n].x, B0[j][n].y);
            }
            if (doL1) {
                #pragma unroll
                for (int n = 0; n < 4; ++n)
                    mma16(acc1[n], a0, a1, a2, a3, B1a[j][n].x, B1a[j][n].y);
            }
        }
        if (doL0) {
            #pragma unroll
            for (int n = 0; n < 4; ++n) {
                int cb = wn * 32 + n * 8 + cbb;
                *(float2*)&red0[r4 * 68 + cb]       = make_float2(acc0[n][0], acc0[n][1]);
                *(float2*)&red0[(r4 + 8) * 68 + cb] = make_float2(acc0[n][2], acc0[n][3]);
            }
        }

        cpa_wait<0>();                   // own As1 quarter done
        pair_bar(barid);

        // ===== L1 h1-part MMAs =====
        if (doL1) {
            #pragma unroll
            for (int j = 0; j < 8; ++j) {
                unsigned a0, a1, a2, a3;
                ldsm4(a0, a1, a2, a3, la1h + (unsigned)(kq * 8 + j) * 32);
                #pragma unroll
                for (int n = 0; n < 4; ++n)
                    mma16(acc1[n], a0, a1, a2, a3, B1b[j][n].x, B1b[j][n].y);
            }
            #pragma unroll
            for (int n = 0; n < 4; ++n) {
                int cb = wn * 32 + n * 8 + cbb;
                *(float2*)&red1[r4 * 68 + cb]       = make_float2(acc1[n][0], acc1[n][1]);
                *(float2*)&red1[(r4 + 8) * 68 + cb] = make_float2(acc1[n][2], acc1[n][3]);
            }
        }

        __syncthreads();                 // red0 + red1 complete

        const int o = fb * 68 + fu * 4;

        // ===== L0 finish + h0 store, then arrive bar0 (critical) ==============
        if (doL0) {
            float4 q0 = *(const float4*)&red[0 * RED_PER + o];
            float4 q1 = *(const float4*)&red[1 * RED_PER + o];
            float4 q2 = *(const float4*)&red[2 * RED_PER + o];
            float4 q3 = *(const float4*)&red[3 * RED_PER + o];
            __half2 zl = *(__half2*)&zraw.x;
            __half2 zh = *(__half2*)&zraw.y;
            float zf = q0.x + q1.x + q2.x + q3.x + __low2float(zl);
            float zi = q0.y + q1.y + q2.y + q3.y + __high2float(zl);
            float zo = q0.z + q1.z + q2.z + q3.z + __low2float(zh);
            float zg = q0.w + q1.w + q2.w + q3.w + __high2float(zh);
            float f  = sigf(zf);
            float ii = sigf(zi);
            float oo = sigf(zo);
            float g  = tanha(zg);
            float c  = f * c0 + ii * g;
            c0 = c;
            float hv = oo * tanha(c);
            ((__half*)d_h0[k & 1])[(bg * 16 + fb) * HID + cg * 16 + fu] =
                __float2half_rn(hv);
        }
        bar_arrive(off0);

        // ===== L1 finish + h1 store, then arrive bar1 (off critical path) =====
        if (doL1) {
            float4 q0 = *(const float4*)&red[4 * RED_PER + o];
            float4 q1 = *(const float4*)&red[5 * RED_PER + o];
            float4 q2 = *(const float4*)&red[6 * RED_PER + o];
            float4 q3 = *(const float4*)&red[7 * RED_PER + o];
            float zf = q0.x + q1.x + q2.x + q3.x + bias1[fu * 4 + 0];
            float zi = q0.y + q1.y + q2.y + q3.y + bias1[fu * 4 + 1];
            float zo = q0.z + q1.z + q2.z + q3.z + bias1[fu * 4 + 2];
            float zg = q0.w + q1.w + q2.w + q3.w + bias1[fu * 4 + 3];
            float f  = sigf(zf);
            float ii = sigf(zi);
            float oo = sigf(zo);
            float g  = tanha(zg);
            float c  = f * c1 + ii * g;
            c1 = c;
            float hv = oo * tanha(c);
            ((__half*)d_h1[(k - 1) & 1])[(bg * 16 + fb) * HID + cg * 16 + fu] =
                __float2half_rn(hv);
        }
        bar_arrive(off1);
    }
}

// ---------------- fc1: smem-staged weight tile, coalesced --------------------
__global__ void __launch_bounds__(256) fc1_kernel(
    const float* __restrict__ fc1w, const float* __restrict__ fc1b)
{
    extern __shared__ unsigned fsm[];
    float*    wsm = (float*)fsm;            // [32][516] padded
    unsigned* hsm = fsm + 32 * 516;         // [16][256] h as half2 words

    const int tid  = threadIdx.x;
    const int bgrp = blockIdx.y;
    const int jbase = blockIdx.x * 32;

    #pragma unroll
    for (int i = tid; i < 4096; i += 256)
        hsm[i] = d_h1[1][bgrp * 4096 + i];
    #pragma unroll
    for (int i = tid; i < 32 * 128; i += 256) {
        int row = i >> 7, k4 = i & 127;
        *(float4*)&wsm[row * 516 + k4 * 4] =
            *(const float4*)&fc1w[(size_t)(jbase + row) * HID + k4 * 4];
    }
    __syncthreads();

    const int j   = tid & 31;
    const int wid = tid >> 5;
    float acc0 = 0.f, acc1 = 0.f;
    const float* wr = wsm + j * 516;
    const unsigned* h0p = hsm + (wid * 2) * 256;
    const unsigned* h1p = hsm + (wid * 2 + 1) * 256;
    #pragma unroll 4
    for (int k4 = 0; k4 < 128; ++k4) {
        float4 wv = *(const float4*)&wr[k4 * 4];
        uint2 hpa = *(const uint2*)(h0p + k4 * 2);
        uint2 hpb = *(const uint2*)(h1p + k4 * 2);
        float2 a0 = __half22float2(*(__half2*)&hpa.x);
        float2 a1 = __half22float2(*(__half2*)&hpa.y);
        float2 b0 = __half22float2(*(__half2*)&hpb.x);
        float2 b1 = __half22float2(*(__half2*)&hpb.y);
        acc0 = fmaf(wv.x, a0.x, acc0); acc0 = fmaf(wv.y, a0.y, acc0);
        acc0 = fmaf(wv.z, a1.x, acc0); acc0 = fmaf(wv.w, a1.y, acc0);
        acc1 = fmaf(wv.x, b0.x, acc1); acc1 = fmaf(wv.y, b0.y, acc1);
        acc1 = fmaf(wv.z, b1.x, acc1); acc1 = fmaf(wv.w, b1.y, acc1);
    }
    float bj = fc1b[jbase + j];
    d_y1[(size_t)(bgrp * 16 + wid * 2)     * HID + jbase + j] = acc0 + bj;
    d_y1[(size_t)(bgrp * 16 + wid * 2 + 1) * HID + jbase + j] = acc1 + bj;
}

// ---------------- fc2 + relu: out[64,24] -----------------------------------------
__global__ void __launch_bounds__(192) fc2_kernel(
    const float* __restrict__ fc2w, const float* __restrict__ fc2b,
    float* __restrict__ out)
{
    __shared__ float ys[HID];
    const int b = blockIdx.x;
    const int tid = threadIdx.x;
    for (int i = tid; i < HID; i += 192) ys[i] = d_y1[(size_t)b * HID + i];
    __syncthreads();
    int j = tid >> 3, part = tid & 7;
    const float4* wr = (const float4*)(fc2w + (size_t)j * HID + part * 64);
    const float4* yv = (const float4*)(ys + part * 64);
    float a = 0.0f;
    #pragma unroll
    for (int kk = 0; kk < 16; ++kk) {
        float4 wv = wr[kk];
        float4 xv = yv[kk];
        a = fmaf(wv.x, xv.x, a);
        a = fmaf(wv.y, xv.y, a);
        a = fmaf(wv.z, xv.z, a);
        a = fmaf(wv.w, xv.w, a);
    }
    a += __shfl_down_sync(0xffffffffu, a, 4, 8);
    a += __shfl_down_sync(0xffffffffu, a, 2, 8);
    a += __shfl_down_sync(0xffffffffu, a, 1, 8);
    if (part == 0)
        out[b * OUTN + j] = fmaxf(a + fc2b[j], 0.0f);
}

// ---------------- launch ---------------------------------------------------------
extern "C" void kernel_launch(void* const* d_in, const int* in_sizes, int n_in,
                              void* d_out, int out_size)
{
    const float* x    = (const float*)d_in[0];
    const float* wf0  = (const float*)d_in[1];
    const float* bf0  = (const float*)d_in[2];
    const float* wi0  = (const float*)d_in[3];
    const float* bi0  = (const float*)d_in[4];
    const float* wo0  = (const float*)d_in[5];
    const float* bo0  = (const float*)d_in[6];
    const float* wg0  = (const float*)d_in[7];
    const float* bg0  = (const float*)d_in[8];
    const float* wf1  = (const float*)d_in[9];
    const float* bf1  = (const float*)d_in[10];
    const float* wi1  = (const float*)d_in[11];
    const float* bi1  = (const float*)d_in[12];
    const float* wo1  = (const float*)d_in[13];
    const float* bo1  = (const float*)d_in[14];
    const float* wg1  = (const float*)d_in[15];
    const float* bg1  = (const float*)d_in[16];
    const float* fc1w = (const float*)d_in[17];
    const float* fc1b = (const float*)d_in[18];
    const float* fc2w = (const float*)d_in[19];
    const float* fc2b = (const float*)d_in[20];
    float* out = (float*)d_out;

    cudaFuncSetAttribute(scan_kernel,
                         cudaFuncAttributeMaxDynamicSharedMemorySize, SMEM_BYTES);
    cudaFuncSetAttribute(xz_gemm_kernel,
                         cudaFuncAttributeMaxDynamicSharedMemorySize, XG_SMEM_BYTES);
    cudaFuncSetAttribute(fc1_kernel,
                         cudaFuncAttributeMaxDynamicSharedMemorySize, FC1_SMEM_BYTES);

    prep_kernel<<<4096, 256>>>(x, wf0, wi0, wo0, wg0, bf0, bi0, bo0, bg0,
                               wf1, wi1, wo1, wg1, bf1, bi1, bo1, bg1);
    dim3 xzgrid(256, 8);
    xz_gemm_kernel<<<xzgrid, NT, XG_SMEM_BYTES>>>();
    scan_kernel<<<NCTA, NT, SMEM_BYTES>>>();
    dim3 fc1grid(16, 4);
    fc1_kernel<<<fc1grid, 256, FC1_SMEM_BYTES>>>(fc1w, fc1b);
    fc2_kernel<<<BATCH, 192>>>(fc2w, fc2b, out);
}

// round 15
// speedup vs baseline: 1.2228x; 1.2228x over previous
#include <cuda_runtime.h>
#include <cuda_fp16.h>
#include <math.h>

#define BATCH 64
#define SEQ   512
#define DIN   128
#define HID   512
#define OUTN  24
#define K0    640
#define K1    1024
#define COLS  2048

#define NCTA   128
#define NBG    4
#define NCTABG 32
#define NT     256
#define NARR   (NCTABG * 8)        // per-warp arrivals per round

// fp16 weight words (u32 = half2) per old-style column-group of 8 units
#define WPW_L0 10240               // 40 k16-blocks * 4 n8-blocks * 64 words
#define WPW_L1 16384               // 64 * 4 * 64
#define WPW    (WPW_L0 + WPW_L1)   // 26624 u32 per cg

#define AS_STRIDE 260              // 256 words (512 fp16) + 4 pad
#define AS_WORDS (16 * AS_STRIDE)  // 4160

// red: 2 layers x 4 kq x [16][68] floats
#define RED_PER   1088
#define RED_FLOATS (8 * RED_PER)

#define SMEM_U32  (2 * AS_WORDS + RED_FLOATS + 64 + 16)
#define SMEM_BYTES (SMEM_U32 * 4)

#define XG_SMEM_U32 (128 * 68 + 16384)
#define XG_SMEM_BYTES (XG_SMEM_U32 * 4)

// fc1: w tile [32][516] floats + h tile [16][256] half2 words
#define FC1_SMEM_U32 (32 * 516 + 4096)
#define FC1_SMEM_BYTES (FC1_SMEM_U32 * 4)

// ---------------- persistent device state ----------------------------------
__device__ __align__(16) unsigned d_Wp[64 * WPW];
__device__ __align__(16) unsigned d_x16[BATCH * SEQ * (DIN / 2)];
__device__ __align__(16) unsigned d_xz[BATCH * SEQ * (COLS / 2)];
__device__ float d_b0r[COLS];
__device__ float d_b1r[COLS];
__device__ __align__(16) unsigned d_h0[2][BATCH * (HID / 2)];
__device__ __align__(16) unsigned d_h1[2][BATCH * (HID / 2)];
__device__ float d_y1[BATCH * HID];
// Fused barrier word per bg: low16 = arrivals (256/round), high16 = round.
__device__ unsigned g_bar[NBG * 32];

__device__ __forceinline__ float tanha(float v) {
    float r; asm("tanh.approx.f32 %0, %1;" : "=f"(r) : "f"(v)); return r;
}
__device__ __forceinline__ float sigf(float v) {
    return 0.5f + 0.5f * tanha(0.5f * v);
}

__device__ __forceinline__ void mma16(float c[4], unsigned a0, unsigned a1,
                                      unsigned a2, unsigned a3,
                                      unsigned b0, unsigned b1)
{
    asm volatile(
        "mma.sync.aligned.m16n8k16.row.col.f32.f16.f16.f32 "
        "{%0,%1,%2,%3},{%4,%5,%6,%7},{%8,%9},{%0,%1,%2,%3};"
        : "+f"(c[0]), "+f"(c[1]), "+f"(c[2]), "+f"(c[3])
        : "r"(a0), "r"(a1), "r"(a2), "r"(a3), "r"(b0), "r"(b1));
}

__device__ __forceinline__ void ldsm4(unsigned& a0, unsigned& a1,
                                      unsigned& a2, unsigned& a3, unsigned addr)
{
    asm volatile(
        "ldmatrix.sync.aligned.m8n8.x4.shared.b16 {%0,%1,%2,%3}, [%4];"
        : "=r"(a0), "=r"(a1), "=r"(a2), "=r"(a3) : "r"(addr));
}

__device__ __forceinline__ void cpa16(void* dst, const void* src)
{
    unsigned d = (unsigned)__cvta_generic_to_shared(dst);
    asm volatile("cp.async.cg.shared.global [%0], [%1], 16;" :: "r"(d), "l"(src));
}
__device__ __forceinline__ void cpa_commit()
{
    asm volatile("cp.async.commit_group;");
}
template<int N>
__device__ __forceinline__ void cpa_wait()
{
    asm volatile("cp.async.wait_group %0;" :: "n"(N));
}
__device__ __forceinline__ void pair_bar(int id)
{
    asm volatile("bar.sync %0, 64;" :: "r"(id) : "memory");
}

// ---------------- prep: weight packing (fp16), x conversion, biases ---------
__global__ void prep_kernel(
    const float* __restrict__ x,
    const float* __restrict__ wf0, const float* __restrict__ wi0,
    const float* __restrict__ wo0, const float* __restrict__ wg0,
    const float* __restrict__ bf0, const float* __restrict__ bi0,
    const float* __restrict__ bo0, const float* __restrict__ bg0,
    const float* __restrict__ wf1, const float* __restrict__ wi1,
    const float* __restrict__ wo1, const float* __restrict__ wg1,
    const float* __restrict__ bf1, const float* __restrict__ bi1,
    const float* __restrict__ bo1, const float* __restrict__ bg1)
{
    const int nW = 64 * WPW;
    const int nX = BATCH * SEQ * (DIN / 2);
    const int ntot = nW + nX + 2 * COLS;
    for (int idx = blockIdx.x * blockDim.x + threadIdx.x; idx < ntot;
         idx += gridDim.x * blockDim.x) {
        if (idx < nW) {
            int cg = idx / WPW;
            int r  = idx % WPW;
            int layer = (r < WPW_L0) ? 0 : 1;
            int rr    = layer ? (r - WPW_L0) : r;
            int kb   = rr >> 8;
            int rem  = rr & 255;
            int nb   = rem >> 6;
            int t    = rem & 63;
            int lane = t >> 1;
            int reg  = t & 1;
            int colloc = nb * 8 + (lane >> 2);
            int unit = cg * 8 + (colloc >> 2);
            int gate = colloc & 3;
            int k    = kb * 16 + (lane & 3) * 2 + reg * 8;
            const float* w;
            int K;
            if (layer == 0) {
                w = (gate == 0) ? wf0 : (gate == 1) ? wi0 : (gate == 2) ? wo0 : wg0;
                K = K0;
            } else {
                w = (gate == 0) ? wf1 : (gate == 1) ? wi1 : (gate == 2) ? wo1 : wg1;
                K = K1;
            }
            __half2 h2 = __floats2half2_rn(w[unit * K + k], w[unit * K + k + 1]);
            d_Wp[idx] = *(unsigned*)&h2;
        } else if (idx < nW + nX) {
            int i = idx - nW;
            __half2 h2 = __floats2half2_rn(x[2 * i], x[2 * i + 1]);
            d_x16[i] = *(unsigned*)&h2;
        } else {
            int col = idx - nW - nX;
            if (col < COLS) {
                int u = col >> 2, g = col & 3;
                const float* bb = (g == 0) ? bf0 : (g == 1) ? bi0 : (g == 2) ? bo0 : bg0;
                d_b0r[col] = bb[u];
            } else {
                col -= COLS;
                int u = col >> 2, g = col & 3;
                const float* bb = (g == 0) ? bf1 : (g == 1) ? bi1 : (g == 2) ? bo1 : bg1;
                d_b1r[col] = bb[u];
            }
        }
    }
}

// ---------------- xz GEMM: xz[b,t,:] = x_t @ Wx0^T + b0 (fp16 out) ----------
__global__ void __launch_bounds__(NT) xz_gemm_kernel()
{
    extern __shared__ unsigned smem_u[];
    unsigned* As = smem_u;                 // [128][68]
    unsigned* Ws = smem_u + 128 * 68;      // 8 cgs * 2048 words

    const int tid  = threadIdx.x;
    const int w    = tid >> 5, lane = tid & 31;
    const int r4   = lane >> 2, kq4 = lane & 3;
    const int row0 = blockIdx.x * 128;
    const int cg0  = blockIdx.y * 8;

    #pragma unroll
    for (int i = tid; i < 2048; i += NT) {
        int row = i >> 4, w4 = (i & 15) * 4;
        cpa16(As + row * 68 + w4, d_x16 + (size_t)(row0 + row) * 64 + w4);
    }
    #pragma unroll
    for (int i = tid; i < 4096; i += NT) {
        int cgL = i >> 9, r = (i & 511) * 4;
        cpa16(Ws + cgL * 2048 + r, d_Wp + (size_t)(cg0 + cgL) * WPW + r);
    }
    cpa_commit();
    cpa_wait<0>();
    __syncthreads();

    float acc[32][4];
    #pragma unroll
    for (int i = 0; i < 32; ++i)
        { acc[i][0] = 0.f; acc[i][1] = 0.f; acc[i][2] = 0.f; acc[i][3] = 0.f; }

    #pragma unroll
    for (int kb = 0; kb < 8; ++kb) {
        const unsigned* ab = As + (w * 16 + r4) * 68 + kb * 8 + kq4;
        unsigned a0 = ab[0];
        unsigned a1 = ab[8 * 68];
        unsigned a2 = ab[4];
        unsigned a3 = ab[8 * 68 + 4];
        #pragma unroll
        for (int j = 0; j < 32; ++j) {
            const unsigned* bp = Ws + (j >> 2) * 2048 + kb * 256 + (j & 3) * 64 + lane * 2;
            uint2 b = *(const uint2*)bp;
            mma16(acc[j], a0, a1, a2, a3, b.x, b.y);
        }
    }

    #pragma unroll
    for (int j = 0; j < 32; ++j) {
        int col = (cg0 + (j >> 2)) * 32 + (j & 3) * 8 + 2 * (lane & 3);
        float bs0 = d_b0r[col], bs1 = d_b0r[col + 1];
        int mrow = row0 + w * 16 + r4;
        __half2 p0 = __floats2half2_rn(acc[j][0] + bs0, acc[j][1] + bs1);
        __half2 p1 = __floats2half2_rn(acc[j][2] + bs0, acc[j][3] + bs1);
        d_xz[(size_t)mrow * 1024 + (col >> 1)]        = *(unsigned*)&p0;
        d_xz[(size_t)(mrow + 8) * 1024 + (col >> 1)]  = *(unsigned*)&p1;
    }
}

// -------- fused single-word barrier, per-WARP arrivals (release/acquire) ------
// Caller: __syncwarp() before warp_arrive (bar.warp.sync gives intra-warp memory
// ordering), lane 0 issues the release-add. Flip when all NARR warps arrived.
__device__ __forceinline__ void warp_arrive(int bg)
{
    __syncwarp();
    if ((threadIdx.x & 31) == 0) {
        unsigned prev;
        asm volatile("atom.release.gpu.global.add.u32 %0, [%1], %2;"
                     : "=r"(prev) : "l"(&g_bar[bg * 32]), "r"(1u) : "memory");
        if ((prev & 0xFFFFu) == NARR - 1) {
            unsigned d;
            asm volatile("atom.release.gpu.global.add.u32 %0, [%1], %2;"
                         : "=r"(d) : "l"(&g_bar[bg * 32]),
                           "r"(0x10000u - NARR) : "memory");
        }
    }
}
// ALL threads poll with acquire loads and resume independently.
__device__ __forceinline__ void bar_wait(int bg, unsigned base, unsigned mygen)
{
    const unsigned* p = &g_bar[bg * 32];
    unsigned v;
    do {
        asm volatile("ld.acquire.gpu.global.u32 %0, [%1];"
                     : "=r"(v) : "l"(p) : "memory");
    } while ((((v >> 16) - base) & 0xFFFFu) < mygen);
}

// ---------------- persistent scan kernel --------------------------------------
// 128 CTAs = 4 batch-groups (16 batches) x 32 unit-groups (16 units = 64 cols)
// warps: 4 K-quarters (kq) x 2 col-halves (wn). L1 K-split is kq-interleaved.
__global__ void __launch_bounds__(NT, 1) scan_kernel()
{
    extern __shared__ unsigned smem_u[];
    unsigned* As0   = smem_u;                    // [16][260]  h0[t]
    unsigned* As1   = As0 + AS_WORDS;            // [16][260]  h1[t-1]
    float*    red   = (float*)(As1 + AS_WORDS);  // [2 layers][4 kq][16][68]
    float*    bias1 = red + RED_FLOATS;          // [64]

    const int tid  = threadIdx.x;
    const int cg   = blockIdx.x & 31;
    const int bg   = blockIdx.x >> 5;
    const int w    = tid >> 5, lane = tid & 31;
    const int wn   = w & 1;                      // col half (32 cols)
    const int kq   = w >> 1;                     // K quarter
    const int r4   = lane >> 2;

    const int fb = tid >> 4, fu = tid & 15;

    // All threads snapshot the round BEFORE this CTA's first arrive (replay-safe).
    unsigned bar_base = (*(volatile unsigned*)&g_bar[bg * 32]) >> 16;

    // ---- one-time: B fragments -> registers ----
    const int cgA = cg * 2 + wn;
    uint2 B0[8][4];       // L0 recurrent: blocks kq*8+j
    uint2 B1a[8][4];      // L1 h0-part:   blocks kq*8+j
    uint2 B1b[8][4];      // L1 h1-part:   blocks 32+kq*8+j
    {
        const unsigned* w0 = d_Wp + (size_t)cgA * WPW + 2048
                           + (kq * 8) * 256 + lane * 2;
        #pragma unroll
        for (int j = 0; j < 8; ++j)
            #pragma unroll
            for (int n = 0; n < 4; ++n)
                B0[j][n] = *(const uint2*)(w0 + j * 256 + n * 64);
        const unsigned* w1 = d_Wp + (size_t)cgA * WPW + WPW_L0
                           + (kq * 8) * 256 + lane * 2;
        #pragma unroll
        for (int j = 0; j < 8; ++j)
            #pragma unroll
            for (int n = 0; n < 4; ++n)
                B1a[j][n] = *(const uint2*)(w1 + j * 256 + n * 64);
        const unsigned* w1b = w1 + 32 * 256;
        #pragma unroll
        for (int j = 0; j < 8; ++j)
            #pragma unroll
            for (int n = 0; n < 4; ++n)
                B1b[j][n] = *(const uint2*)(w1b + j * 256 + n * 64);
    }
    if (tid < 64) bias1[tid] = d_b1r[cg * 64 + tid];

    // zero this bg's t=-1 hidden rows
    {
        int idx = cg * NT + tid;
        if (idx < 4096) d_h0[1][bg * 4096 + idx] = 0u;
        else            d_h1[1][bg * 4096 + (idx - 4096)] = 0u;
    }
    float c0 = 0.0f, c1 = 0.0f;
    __syncthreads();                 // bias1 visible to all warps before loop
    warp_arrive(bg);
    unsigned mygen = 1;

    // ldmatrix per-lane addresses (blocks kq*8+j live in quarter kq)
    unsigned smem_base = (unsigned)__cvta_generic_to_shared(smem_u);
    const int lrow = lane & 15;
    const int lcol = (lane >> 4) * 4;
    const unsigned la0  = smem_base + (unsigned)(lrow * AS_STRIDE + lcol) * 4;
    const unsigned la1h = la0 + AS_WORDS * 4;    // same pattern in As1

    float* red0 = red + kq * RED_PER;
    float* red1 = red + 4 * RED_PER + kq * RED_PER;
    const int barid = 1 + kq;

    for (int k = 0; k <= SEQ; ++k) {
        const int doL0 = (k < SEQ);
        const int doL1 = (k >= 1);

        // xz prefetch (no dependency on h) — overlap with barrier propagation
        uint2 zraw;
        if (doL0)
            zraw = *(const uint2*)(d_xz +
                    (size_t)((bg * 16 + fb) * SEQ + k) * 1024 + cg * 32 + fu * 2);

        bar_wait(bg, bar_base, mygen); ++mygen;

        // ===== self-staging: warp (kq,wn) stages its own 8 rows x quarter kq ===
        {
            const unsigned* __restrict__ h0prev = d_h0[(k + 1) & 1];
            #pragma unroll
            for (int it = 0; it < 4; ++it) {
                int idx = it * 32 + lane;            // 0..127
                int row = wn * 8 + (idx >> 4);
                int wd  = kq * 64 + (idx & 15) * 4;
                cpa16(As0 + row * AS_STRIDE + wd,
                      h0prev + (bg * 16 + row) * 256 + wd);
            }
        }
        cpa_commit();
        if (doL1) {
            const unsigned* __restrict__ h1prev = d_h1[k & 1];
            #pragma unroll
            for (int it = 0; it < 4; ++it) {
                int idx = it * 32 + lane;
                int row = wn * 8 + (idx >> 4);
                int wd  = kq * 64 + (idx & 15) * 4;
                cpa16(As1 + row * AS_STRIDE + wd,
                      h1prev + (bg * 16 + row) * 256 + wd);
            }
        }
        cpa_commit();                    // always commit (possibly empty group)

        cpa_wait<1>();                   // own As0 quarter done
        pair_bar(barid);                 // partner's half of the quarter done

        const int cbb = 2 * (lane & 3);

        // ===== fused pass over As0: L0 MMA + L1 h0-part MMA share fragments ===
        float acc0[4][4] = {};
        float acc1[4][4] = {};
        #pragma unroll
        for (int j = 0; j < 8; ++j) {
            unsigned a0, a1, a2, a3;
            ldsm4(a0, a1, a2, a3, la0 + (unsigned)(kq * 8 + j) * 32);
            if (doL0) {
                #pragma unroll
                for (int n = 0; n < 4; ++n)
                    mma16(acc0[n], a0, a1, a2, a3, B0[j][n].x, B0[j][n].y);
            }
            if (doL1) {
                #pragma unroll
                for (int n = 0; n < 4; ++n)
                    mma16(acc1[n], a0, a1, a2, a3, B1a[j][n].x, B1a[j][n].y);
            }
        }
        if (doL0) {
            #pragma unroll
            for (int n = 0; n < 4; ++n) {
                int cb = wn * 32 + n * 8 + cbb;
                *(float2*)&red0[r4 * 68 + cb]       = make_float2(acc0[n][0], acc0[n][1]);
                *(float2*)&red0[(r4 + 8) * 68 + cb] = make_float2(acc0[n][2], acc0[n][3]);
            }
        }

        cpa_wait<0>();                   // own As1 quarter done
        pair_bar(barid);

        // ===== L1 h1-part MMAs =====
        if (doL1) {
            #pragma unroll
            for (int j = 0; j < 8; ++j) {
                unsigned a0, a1, a2, a3;
                ldsm4(a0, a1, a2, a3, la1h + (unsigned)(kq * 8 + j) * 32);
                #pragma unroll
                for (int n = 0; n < 4; ++n)
                    mma16(acc1[n], a0, a1, a2, a3, B1b[j][n].x, B1b[j][n].y);
            }
            #pragma unroll
            for (int n = 0; n < 4; ++n) {
                int cb = wn * 32 + n * 8 + cbb;
                *(float2*)&red1[r4 * 68 + cb]       = make_float2(acc1[n][0], acc1[n][1]);
                *(float2*)&red1[(r4 + 8) * 68 + cb] = make_float2(acc1[n][2], acc1[n][3]);
            }
        }

        __syncthreads();                 // red0 + red1 complete, all warps

        // ===== pointwise finishes =====
        const int o = fb * 68 + fu * 4;
        if (doL0) {
            float4 q0 = *(const float4*)&red[0 * RED_PER + o];
            float4 q1 = *(const float4*)&red[1 * RED_PER + o];
            float4 q2 = *(const float4*)&red[2 * RED_PER + o];
            float4 q3 = *(const float4*)&red[3 * RED_PER + o];
            __half2 zl = *(__half2*)&zraw.x;
            __half2 zh = *(__half2*)&zraw.y;
            float zf = q0.x + q1.x + q2.x + q3.x + __low2float(zl);
            float zi = q0.y + q1.y + q2.y + q3.y + __high2float(zl);
            float zo = q0.z + q1.z + q2.z + q3.z + __low2float(zh);
            float zg = q0.w + q1.w + q2.w + q3.w + __high2float(zh);
            float f  = sigf(zf);
            float ii = sigf(zi);
            float oo = sigf(zo);
            float g  = tanha(zg);
            float c  = f * c0 + ii * g;
            c0 = c;
            float hv = oo * tanha(c);
            ((__half*)d_h0[k & 1])[(bg * 16 + fb) * HID + cg * 16 + fu] =
                __float2half_rn(hv);
        }
        if (doL1) {
            float4 q0 = *(const float4*)&red[4 * RED_PER + o];
            float4 q1 = *(const float4*)&red[5 * RED_PER + o];
            float4 q2 = *(const float4*)&red[6 * RED_PER + o];
            float4 q3 = *(const float4*)&red[7 * RED_PER + o];
            float zf = q0.x + q1.x + q2.x + q3.x + bias1[fu * 4 + 0];
            float zi = q0.y + q1.y + q2.y + q3.y + bias1[fu * 4 + 1];
            float zo = q0.z + q1.z + q2.z + q3.z + bias1[fu * 4 + 2];
            float zg = q0.w + q1.w + q2.w + q3.w + bias1[fu * 4 + 3];
            float f  = sigf(zf);
            float ii = sigf(zi);
            float oo = sigf(zo);
            float g  = tanha(zg);
            float c  = f * c1 + ii * g;
            c1 = c;
            float hv = oo * tanha(c);
            ((__half*)d_h1[(k - 1) & 1])[(bg * 16 + fb) * HID + cg * 16 + fu] =
                __float2half_rn(hv);
        }

        warp_arrive(bg);                 // per-warp: no extra __syncthreads
    }
}

// ---------------- fc1: smem-staged weight tile, coalesced --------------------
__global__ void __launch_bounds__(256) fc1_kernel(
    const float* __restrict__ fc1w, const float* __restrict__ fc1b)
{
    extern __shared__ unsigned fsm[];
    float*    wsm = (float*)fsm;            // [32][516] padded
    unsigned* hsm = fsm + 32 * 516;         // [16][256] h as half2 words

    const int tid  = threadIdx.x;
    const int bgrp = blockIdx.y;
    const int jbase = blockIdx.x * 32;

    #pragma unroll
    for (int i = tid; i < 4096; i += 256)
        hsm[i] = d_h1[1][bgrp * 4096 + i];
    #pragma unroll
    for (int i = tid; i < 32 * 128; i += 256) {
        int row = i >> 7, k4 = i & 127;
        *(float4*)&wsm[row * 516 + k4 * 4] =
            *(const float4*)&fc1w[(size_t)(jbase + row) * HID + k4 * 4];
    }
    __syncthreads();

    const int j   = tid & 31;
    const int wid = tid >> 5;
    float acc0 = 0.f, acc1 = 0.f;
    const float* wr = wsm + j * 516;
    const unsigned* h0p = hsm + (wid * 2) * 256;
    const unsigned* h1p = hsm + (wid * 2 + 1) * 256;
    #pragma unroll 4
    for (int k4 = 0; k4 < 128; ++k4) {
        float4 wv = *(const float4*)&wr[k4 * 4];
        uint2 hpa = *(const uint2*)(h0p + k4 * 2);
        uint2 hpb = *(const uint2*)(h1p + k4 * 2);
        float2 a0 = __half22float2(*(__half2*)&hpa.x);
        float2 a1 = __half22float2(*(__half2*)&hpa.y);
        float2 b0 = __half22float2(*(__half2*)&hpb.x);
        float2 b1 = __half22float2(*(__half2*)&hpb.y);
        acc0 = fmaf(wv.x, a0.x, acc0); acc0 = fmaf(wv.y, a0.y, acc0);
        acc0 = fmaf(wv.z, a1.x, acc0); acc0 = fmaf(wv.w, a1.y, acc0);
        acc1 = fmaf(wv.x, b0.x, acc1); acc1 = fmaf(wv.y, b0.y, acc1);
        acc1 = fmaf(wv.z, b1.x, acc1); acc1 = fmaf(wv.w, b1.y, acc1);
    }
    float bj = fc1b[jbase + j];
    d_y1[(size_t)(bgrp * 16 + wid * 2)     * HID + jbase + j] = acc0 + bj;
    d_y1[(size_t)(bgrp * 16 + wid * 2 + 1) * HID + jbase + j] = acc1 + bj;
}

// ---------------- fc2 + relu: out[64,24] -----------------------------------------
__global__ void __launch_bounds__(192) fc2_kernel(
    const float* __restrict__ fc2w, const float* __restrict__ fc2b,
    float* __restrict__ out)
{
    __shared__ float ys[HID];
    const int b = blockIdx.x;
    const int tid = threadIdx.x;
    for (int i = tid; i < HID; i += 192) ys[i] = d_y1[(size_t)b * HID + i];
    __syncthreads();
    int j = tid >> 3, part = tid & 7;
    const float4* wr = (const float4*)(fc2w + (size_t)j * HID + part * 64);
    const float4* yv = (const float4*)(ys + part * 64);
    float a = 0.0f;
    #pragma unroll
    for (int kk = 0; kk < 16; ++kk) {
        float4 wv = wr[kk];
        float4 xv = yv[kk];
        a = fmaf(wv.x, xv.x, a);
        a = fmaf(wv.y, xv.y, a);
        a = fmaf(wv.z, xv.z, a);
        a = fmaf(wv.w, xv.w, a);
    }
    a += __shfl_down_sync(0xffffffffu, a, 4, 8);
    a += __shfl_down_sync(0xffffffffu, a, 2, 8);
    a += __shfl_down_sync(0xffffffffu, a, 1, 8);
    if (part == 0)
        out[b * OUTN + j] = fmaxf(a + fc2b[j], 0.0f);
}

// ---------------- launch ---------------------------------------------------------
extern "C" void kernel_launch(void* const* d_in, const int* in_sizes, int n_in,
                              void* d_out, int out_size)
{
    const float* x    = (const float*)d_in[0];
    const float* wf0  = (const float*)d_in[1];
    const float* bf0  = (const float*)d_in[2];
    const float* wi0  = (const float*)d_in[3];
    const float* bi0  = (const float*)d_in[4];
    const float* wo0  = (const float*)d_in[5];
    const float* bo0  = (const float*)d_in[6];
    const float* wg0  = (const float*)d_in[7];
    const float* bg0  = (const float*)d_in[8];
    const float* wf1  = (const float*)d_in[9];
    const float* bf1  = (const float*)d_in[10];
    const float* wi1  = (const float*)d_in[11];
    const float* bi1  = (const float*)d_in[12];
    const float* wo1  = (const float*)d_in[13];
    const float* bo1  = (const float*)d_in[14];
    const float* wg1  = (const float*)d_in[15];
    const float* bg1  = (const float*)d_in[16];
    const float* fc1w = (const float*)d_in[17];
    const float* fc1b = (const float*)d_in[18];
    const float* fc2w = (const float*)d_in[19];
    const float* fc2b = (const float*)d_in[20];
    float* out = (float*)d_out;

    cudaFuncSetAttribute(scan_kernel,
                         cudaFuncAttributeMaxDynamicSharedMemorySize, SMEM_BYTES);
    cudaFuncSetAttribute(xz_gemm_kernel,
                         cudaFuncAttributeMaxDynamicSharedMemorySize, XG_SMEM_BYTES);
    cudaFuncSetAttribute(fc1_kernel,
                         cudaFuncAttributeMaxDynamicSharedMemorySize, FC1_SMEM_BYTES);

    prep_kernel<<<4096, 256>>>(x, wf0, wi0, wo0, wg0, bf0, bi0, bo0, bg0,
                               wf1, wi1, wo1, wg1, bf1, bi1, bo1, bg1);
    dim3 xzgrid(256, 8);
    xz_gemm_kernel<<<xzgrid, NT, XG_SMEM_BYTES>>>();
    scan_kernel<<<NCTA, NT, SMEM_BYTES>>>();
    dim3 fc1grid(16, 4);
    fc1_kernel<<<fc1grid, 256, FC1_SMEM_BYTES>>>(fc1w, fc1b);
    fc2_kernel<<<BATCH, 192>>>(fc2w, fc2b, out);
}

// round 16
// speedup vs baseline: 1.2492x; 1.0216x over previous
#include <cuda_runtime.h>
#include <cuda_fp16.h>
#include <math.h>

#define BATCH 64
#define SEQ   512
#define DIN   128
#define HID   512
#define OUTN  24
#define K0    640
#define K1    1024
#define COLS  2048

#define NCTA   128
#define NBG    4
#define NCTABG 32
#define NT     256

// fp16 weight words (u32 = half2) per old-style column-group of 8 units
#define WPW_L0 10240               // 40 k16-blocks * 4 n8-blocks * 64 words
#define WPW_L1 16384               // 64 * 4 * 64
#define WPW    (WPW_L0 + WPW_L1)   // 26624 u32 per cg

#define AS_STRIDE 260              // 256 words (512 fp16) + 4 pad
#define AS_WORDS (16 * AS_STRIDE)  // 4160

// red: 2 layers x 4 kq x [16][68] floats
#define RED_PER   1088
#define RED_FLOATS (8 * RED_PER)

#define SMEM_U32  (2 * AS_WORDS + RED_FLOATS + 64 + 16)
#define SMEM_BYTES (SMEM_U32 * 4)

#define XG_SMEM_U32 (128 * 68 + 16384)
#define XG_SMEM_BYTES (XG_SMEM_U32 * 4)

// fc1: w tile [32][516] floats + h tile [16][256] half2 words
#define FC1_SMEM_U32 (32 * 516 + 4096)
#define FC1_SMEM_BYTES (FC1_SMEM_U32 * 4)

// ---------------- persistent device state ----------------------------------
__device__ __align__(16) unsigned d_Wp[64 * WPW];
__device__ __align__(16) unsigned d_x16[BATCH * SEQ * (DIN / 2)];
__device__ __align__(16) unsigned d_xz[BATCH * SEQ * (COLS / 2)];
__device__ float d_b0r[COLS];
__device__ float d_b1r[COLS];
__device__ __align__(16) unsigned d_h0[2][BATCH * (HID / 2)];
__device__ __align__(16) unsigned d_h1[2][BATCH * (HID / 2)];
__device__ float d_y1[BATCH * HID];
// Fused barrier word per bg: low16 = CTA arrivals (32/round), high16 = round.
__device__ unsigned g_bar[NBG * 32];

__device__ __forceinline__ float tanha(float v) {
    float r; asm("tanh.approx.f32 %0, %1;" : "=f"(r) : "f"(v)); return r;
}
__device__ __forceinline__ float sigf(float v) {
    return 0.5f + 0.5f * tanha(0.5f * v);
}

__device__ __forceinline__ void mma16(float c[4], unsigned a0, unsigned a1,
                                      unsigned a2, unsigned a3,
                                      unsigned b0, unsigned b1)
{
    asm volatile(
        "mma.sync.aligned.m16n8k16.row.col.f32.f16.f16.f32 "
        "{%0,%1,%2,%3},{%4,%5,%6,%7},{%8,%9},{%0,%1,%2,%3};"
        : "+f"(c[0]), "+f"(c[1]), "+f"(c[2]), "+f"(c[3])
        : "r"(a0), "r"(a1), "r"(a2), "r"(a3), "r"(b0), "r"(b1));
}

__device__ __forceinline__ void ldsm4(unsigned& a0, unsigned& a1,
                                      unsigned& a2, unsigned& a3, unsigned addr)
{
    asm volatile(
        "ldmatrix.sync.aligned.m8n8.x4.shared.b16 {%0,%1,%2,%3}, [%4];"
        : "=r"(a0), "=r"(a1), "=r"(a2), "=r"(a3) : "r"(addr));
}

__device__ __forceinline__ void cpa16(void* dst, const void* src)
{
    unsigned d = (unsigned)__cvta_generic_to_shared(dst);
    asm volatile("cp.async.cg.shared.global [%0], [%1], 16;" :: "r"(d), "l"(src));
}
__device__ __forceinline__ void cpa_commit()
{
    asm volatile("cp.async.commit_group;");
}
template<int N>
__device__ __forceinline__ void cpa_wait()
{
    asm volatile("cp.async.wait_group %0;" :: "n"(N));
}
__device__ __forceinline__ void pair_bar(int id)
{
    asm volatile("bar.sync %0, 64;" :: "r"(id) : "memory");
}

// ---------------- prep: weight packing (fp16), x conversion, biases ---------
__global__ void prep_kernel(
    const float* __restrict__ x,
    const float* __restrict__ wf0, const float* __restrict__ wi0,
    const float* __restrict__ wo0, const float* __restrict__ wg0,
    const float* __restrict__ bf0, const float* __restrict__ bi0,
    const float* __restrict__ bo0, const float* __restrict__ bg0,
    const float* __restrict__ wf1, const float* __restrict__ wi1,
    const float* __restrict__ wo1, const float* __restrict__ wg1,
    const float* __restrict__ bf1, const float* __restrict__ bi1,
    const float* __restrict__ bo1, const float* __restrict__ bg1)
{
    const int nW = 64 * WPW;
    const int nX = BATCH * SEQ * (DIN / 2);
    const int ntot = nW + nX + 2 * COLS;
    for (int idx = blockIdx.x * blockDim.x + threadIdx.x; idx < ntot;
         idx += gridDim.x * blockDim.x) {
        if (idx < nW) {
            int cg = idx / WPW;
            int r  = idx % WPW;
            int layer = (r < WPW_L0) ? 0 : 1;
            int rr    = layer ? (r - WPW_L0) : r;
            int kb   = rr >> 8;
            int rem  = rr & 255;
            int nb   = rem >> 6;
            int t    = rem & 63;
            int lane = t >> 1;
            int reg  = t & 1;
            int colloc = nb * 8 + (lane >> 2);
            int unit = cg * 8 + (colloc >> 2);
            int gate = colloc & 3;
            int k    = kb * 16 + (lane & 3) * 2 + reg * 8;
            const float* w;
            int K;
            if (layer == 0) {
                w = (gate == 0) ? wf0 : (gate == 1) ? wi0 : (gate == 2) ? wo0 : wg0;
                K = K0;
            } else {
                w = (gate == 0) ? wf1 : (gate == 1) ? wi1 : (gate == 2) ? wo1 : wg1;
                K = K1;
            }
            __half2 h2 = __floats2half2_rn(w[unit * K + k], w[unit * K + k + 1]);
            d_Wp[idx] = *(unsigned*)&h2;
        } else if (idx < nW + nX) {
            int i = idx - nW;
            __half2 h2 = __floats2half2_rn(x[2 * i], x[2 * i + 1]);
            d_x16[i] = *(unsigned*)&h2;
        } else {
            int col = idx - nW - nX;
            if (col < COLS) {
                int u = col >> 2, g = col & 3;
                const float* bb = (g == 0) ? bf0 : (g == 1) ? bi0 : (g == 2) ? bo0 : bg0;
                d_b0r[col] = bb[u];
            } else {
                col -= COLS;
                int u = col >> 2, g = col & 3;
                const float* bb = (g == 0) ? bf1 : (g == 1) ? bi1 : (g == 2) ? bo1 : bg1;
                d_b1r[col] = bb[u];
            }
        }
    }
}

// ---------------- xz GEMM: xz[b,t,:] = x_t @ Wx0^T + b0 (fp16 out) ----------
__global__ void __launch_bounds__(NT) xz_gemm_kernel()
{
    extern __shared__ unsigned smem_u[];
    unsigned* As = smem_u;                 // [128][68]
    unsigned* Ws = smem_u + 128 * 68;      // 8 cgs * 2048 words

    const int tid  = threadIdx.x;
    const int w    = tid >> 5, lane = tid & 31;
    const int r4   = lane >> 2, kq4 = lane & 3;
    const int row0 = blockIdx.x * 128;
    const int cg0  = blockIdx.y * 8;

    #pragma unroll
    for (int i = tid; i < 2048; i += NT) {
        int row = i >> 4, w4 = (i & 15) * 4;
        cpa16(As + row * 68 + w4, d_x16 + (size_t)(row0 + row) * 64 + w4);
    }
    #pragma unroll
    for (int i = tid; i < 4096; i += NT) {
        int cgL = i >> 9, r = (i & 511) * 4;
        cpa16(Ws + cgL * 2048 + r, d_Wp + (size_t)(cg0 + cgL) * WPW + r);
    }
    cpa_commit();
    cpa_wait<0>();
    __syncthreads();

    float acc[32][4];
    #pragma unroll
    for (int i = 0; i < 32; ++i)
        { acc[i][0] = 0.f; acc[i][1] = 0.f; acc[i][2] = 0.f; acc[i][3] = 0.f; }

    #pragma unroll
    for (int kb = 0; kb < 8; ++kb) {
        const unsigned* ab = As + (w * 16 + r4) * 68 + kb * 8 + kq4;
        unsigned a0 = ab[0];
        unsigned a1 = ab[8 * 68];
        unsigned a2 = ab[4];
        unsigned a3 = ab[8 * 68 + 4];
        #pragma unroll
        for (int j = 0; j < 32; ++j) {
            const unsigned* bp = Ws + (j >> 2) * 2048 + kb * 256 + (j & 3) * 64 + lane * 2;
            uint2 b = *(const uint2*)bp;
            mma16(acc[j], a0, a1, a2, a3, b.x, b.y);
        }
    }

    #pragma unroll
    for (int j = 0; j < 32; ++j) {
        int col = (cg0 + (j >> 2)) * 32 + (j & 3) * 8 + 2 * (lane & 3);
        float bs0 = d_b0r[col], bs1 = d_b0r[col + 1];
        int mrow = row0 + w * 16 + r4;
        __half2 p0 = __floats2half2_rn(acc[j][0] + bs0, acc[j][1] + bs1);
        __half2 p1 = __floats2half2_rn(acc[j][2] + bs0, acc[j][3] + bs1);
        d_xz[(size_t)mrow * 1024 + (col >> 1)]        = *(unsigned*)&p0;
        d_xz[(size_t)(mrow + 8) * 1024 + (col >> 1)]  = *(unsigned*)&p1;
    }
}

// -------- two-level arrive: warps aggregate in smem, last warp hits L2 --------
// Chain: warp stores ->(syncwarp)-> lane0 atom.acq_rel.cta.shared (+1)
//   -> 8th warp (prev&7==7) acquires all CTA warps' arrivals
//   -> single atom.release.gpu.global (+1); flip when 32 CTAs arrived.
// Scoped release/acquire edges are transitive -> waiter sees all h stores.
__device__ __forceinline__ void warp_arrive(int bg, unsigned saddr)
{
    __syncwarp();
    if ((threadIdx.x & 31) == 0) {
        unsigned prev;
        asm volatile("atom.acq_rel.cta.shared.add.u32 %0, [%1], %2;"
                     : "=r"(prev) : "r"(saddr), "r"(1u) : "memory");
        if ((prev & 7u) == 7u) {           // last of 8 warps this round
            unsigned gprev;
            asm volatile("atom.release.gpu.global.add.u32 %0, [%1], %2;"
                         : "=r"(gprev) : "l"(&g_bar[bg * 32]), "r"(1u) : "memory");
            if ((gprev & 0xFFFFu) == NCTABG - 1) {
                unsigned d;
                asm volatile("atom.release.gpu.global.add.u32 %0, [%1], %2;"
                             : "=r"(d) : "l"(&g_bar[bg * 32]),
                               "r"(0x10000u - NCTABG) : "memory");
            }
        }
    }
}
// ALL threads poll with acquire loads and resume independently.
__device__ __forceinline__ void bar_wait(int bg, unsigned base, unsigned mygen)
{
    const unsigned* p = &g_bar[bg * 32];
    unsigned v;
    do {
        asm volatile("ld.acquire.gpu.global.u32 %0, [%1];"
                     : "=r"(v) : "l"(p) : "memory");
    } while ((((v >> 16) - base) & 0xFFFFu) < mygen);
}

// ---------------- persistent scan kernel --------------------------------------
// 128 CTAs = 4 batch-groups (16 batches) x 32 unit-groups (16 units = 64 cols)
// warps: 4 K-quarters (kq) x 2 col-halves (wn). L1 K-split is kq-interleaved.
__global__ void __launch_bounds__(NT, 1) scan_kernel()
{
    extern __shared__ unsigned smem_u[];
    unsigned* As0   = smem_u;                    // [16][260]  h0[t]
    unsigned* As1   = As0 + AS_WORDS;            // [16][260]  h1[t-1]
    float*    red   = (float*)(As1 + AS_WORDS);  // [2 layers][4 kq][16][68]
    float*    bias1 = red + RED_FLOATS;          // [64]
    __shared__ unsigned s_arr;                   // CTA arrive counter (monotonic)

    const int tid  = threadIdx.x;
    const int cg   = blockIdx.x & 31;
    const int bg   = blockIdx.x >> 5;
    const int w    = tid >> 5, lane = tid & 31;
    const int wn   = w & 1;                      // col half (32 cols)
    const int kq   = w >> 1;                     // K quarter
    const int r4   = lane >> 2;

    const int fb = tid >> 4, fu = tid & 15;

    // All threads snapshot the round BEFORE this CTA's first arrive (replay-safe).
    unsigned bar_base = (*(volatile unsigned*)&g_bar[bg * 32]) >> 16;
    if (tid == 0) s_arr = 0;
    const unsigned sarr_addr = (unsigned)__cvta_generic_to_shared(&s_arr);

    // ---- one-time: B fragments -> registers ----
    const int cgA = cg * 2 + wn;
    uint2 B0[8][4];       // L0 recurrent: blocks kq*8+j
    uint2 B1a[8][4];      // L1 h0-part:   blocks kq*8+j
    uint2 B1b[8][4];      // L1 h1-part:   blocks 32+kq*8+j
    {
        const unsigned* w0 = d_Wp + (size_t)cgA * WPW + 2048
                           + (kq * 8) * 256 + lane * 2;
        #pragma unroll
        for (int j = 0; j < 8; ++j)
            #pragma unroll
            for (int n = 0; n < 4; ++n)
                B0[j][n] = *(const uint2*)(w0 + j * 256 + n * 64);
        const unsigned* w1 = d_Wp + (size_t)cgA * WPW + WPW_L0
                           + (kq * 8) * 256 + lane * 2;
        #pragma unroll
        for (int j = 0; j < 8; ++j)
            #pragma unroll
            for (int n = 0; n < 4; ++n)
                B1a[j][n] = *(const uint2*)(w1 + j * 256 + n * 64);
        const unsigned* w1b = w1 + 32 * 256;
        #pragma unroll
        for (int j = 0; j < 8; ++j)
            #pragma unroll
            for (int n = 0; n < 4; ++n)
                B1b[j][n] = *(const uint2*)(w1b + j * 256 + n * 64);
    }
    if (tid < 64) bias1[tid] = d_b1r[cg * 64 + tid];

    // zero this bg's t=-1 hidden rows
    {
        int idx = cg * NT + tid;
        if (idx < 4096) d_h0[1][bg * 4096 + idx] = 0u;
        else            d_h1[1][bg * 4096 + (idx - 4096)] = 0u;
    }
    float c0 = 0.0f, c1 = 0.0f;
    __syncthreads();                 // bias1 + s_arr init visible to all warps
    warp_arrive(bg, sarr_addr);
    unsigned mygen = 1;

    // ldmatrix per-lane addresses (blocks kq*8+j live in quarter kq)
    unsigned smem_base = (unsigned)__cvta_generic_to_shared(smem_u);
    const int lrow = lane & 15;
    const int lcol = (lane >> 4) * 4;
    const unsigned la0  = smem_base + (unsigned)(lrow * AS_STRIDE + lcol) * 4;
    const unsigned la1h = la0 + AS_WORDS * 4;    // same pattern in As1

    float* red0 = red + kq * RED_PER;
    float* red1 = red + 4 * RED_PER + kq * RED_PER;
    const int barid = 1 + kq;

    for (int k = 0; k <= SEQ; ++k) {
        const int doL0 = (k < SEQ);
        const int doL1 = (k >= 1);

        // xz prefetch (no dependency on h) — overlap with barrier propagation
        uint2 zraw;
        if (doL0)
            zraw = *(const uint2*)(d_xz +
                    (size_t)((bg * 16 + fb) * SEQ + k) * 1024 + cg * 32 + fu * 2);

        bar_wait(bg, bar_base, mygen); ++mygen;

        // ===== self-staging: warp (kq,wn) stages its own 8 rows x quarter kq ===
        {
            const unsigned* __restrict__ h0prev = d_h0[(k + 1) & 1];
            #pragma unroll
            for (int it = 0; it < 4; ++it) {
                int idx = it * 32 + lane;            // 0..127
                int row = wn * 8 + (idx >> 4);
                int wd  = kq * 64 + (idx & 15) * 4;
                cpa16(As0 + row * AS_STRIDE + wd,
                      h0prev + (bg * 16 + row) * 256 + wd);
            }
        }
        cpa_commit();
        if (doL1) {
            const unsigned* __restrict__ h1prev = d_h1[k & 1];
            #pragma unroll
            for (int it = 0; it < 4; ++it) {
                int idx = it * 32 + lane;
                int row = wn * 8 + (idx >> 4);
                int wd  = kq * 64 + (idx & 15) * 4;
                cpa16(As1 + row * AS_STRIDE + wd,
                      h1prev + (bg * 16 + row) * 256 + wd);
            }
        }
        cpa_commit();                    // always commit (possibly empty group)

        cpa_wait<1>();                   // own As0 quarter done
        pair_bar(barid);                 // partner's half of the quarter done

        const int cbb = 2 * (lane & 3);

        // ===== fused pass over As0: L0 MMA + L1 h0-part MMA share fragments ===
        float acc0[4][4] = {};
        float acc1[4][4] = {};
        #pragma unroll
        for (int j = 0; j < 8; ++j) {
            unsigned a0, a1, a2, a3;
            ldsm4(a0, a1, a2, a3, la0 + (unsigned)(kq * 8 + j) * 32);
            if (doL0) {
                #pragma unroll
                for (int n = 0; n < 4; ++n)
                    mma16(acc0[n], a0, a1, a2, a3, B0[j][n].x, B0[j][n].y);
            }
            if (doL1) {
                #pragma unroll
                for (int n = 0; n < 4; ++n)
                    mma16(acc1[n], a0, a1, a2, a3, B1a[j][n].x, B1a[j][n].y);
            }
        }
        if (doL0) {
            #pragma unroll
            for (int n = 0; n < 4; ++n) {
                int cb = wn * 32 + n * 8 + cbb;
                *(float2*)&red0[r4 * 68 + cb]       = make_float2(acc0[n][0], acc0[n][1]);
                *(float2*)&red0[(r4 + 8) * 68 + cb] = make_float2(acc0[n][2], acc0[n][3]);
            }
        }

        cpa_wait<0>();                   // own As1 quarter done
        pair_bar(barid);

        // ===== L1 h1-part MMAs =====
        if (doL1) {
            #pragma unroll
            for (int j = 0; j < 8; ++j) {
                unsigned a0, a1, a2, a3;
                ldsm4(a0, a1, a2, a3, la1h + (unsigned)(kq * 8 + j) * 32);
                #pragma unroll
                for (int n = 0; n < 4; ++n)
                    mma16(acc1[n], a0, a1, a2, a3, B1b[j][n].x, B1b[j][n].y);
            }
            #pragma unroll
            for (int n = 0; n < 4; ++n) {
                int cb = wn * 32 + n * 8 + cbb;
                *(float2*)&red1[r4 * 68 + cb]       = make_float2(acc1[n][0], acc1[n][1]);
                *(float2*)&red1[(r4 + 8) * 68 + cb] = make_float2(acc1[n][2], acc1[n][3]);
            }
        }

        __syncthreads();                 // red0 + red1 complete, all warps

        // ===== pointwise finishes =====
        const int o = fb * 68 + fu * 4;
        if (doL0) {
            float4 q0 = *(const float4*)&red[0 * RED_PER + o];
            float4 q1 = *(const float4*)&red[1 * RED_PER + o];
            float4 q2 = *(const float4*)&red[2 * RED_PER + o];
            float4 q3 = *(const float4*)&red[3 * RED_PER + o];
            __half2 zl = *(__half2*)&zraw.x;
            __half2 zh = *(__half2*)&zraw.y;
            float zf = q0.x + q1.x + q2.x + q3.x + __low2float(zl);
            float zi = q0.y + q1.y + q2.y + q3.y + __high2float(zl);
            float zo = q0.z + q1.z + q2.z + q3.z + __low2float(zh);
            float zg = q0.w + q1.w + q2.w + q3.w + __high2float(zh);
            float f  = sigf(zf);
            float ii = sigf(zi);
            float oo = sigf(zo);
            float g  = tanha(zg);
            float c  = f * c0 + ii * g;
            c0 = c;
            float hv = oo * tanha(c);
            ((__half*)d_h0[k & 1])[(bg * 16 + fb) * HID + cg * 16 + fu] =
                __float2half_rn(hv);
        }
        if (doL1) {
            float4 q0 = *(const float4*)&red[4 * RED_PER + o];
            float4 q1 = *(const float4*)&red[5 * RED_PER + o];
            float4 q2 = *(const float4*)&red[6 * RED_PER + o];
            float4 q3 = *(const float4*)&red[7 * RED_PER + o];
            float zf = q0.x + q1.x + q2.x + q3.x + bias1[fu * 4 + 0];
            float zi = q0.y + q1.y + q2.y + q3.y + bias1[fu * 4 + 1];
            float zo = q0.z + q1.z + q2.z + q3.z + bias1[fu * 4 + 2];
            float zg = q0.w + q1.w + q2.w + q3.w + bias1[fu * 4 + 3];
            float f  = sigf(zf);
            float ii = sigf(zi);
            float oo = sigf(zo);
            float g  = tanha(zg);
            float c  = f * c1 + ii * g;
            c1 = c;
            float hv = oo * tanha(c);
            ((__half*)d_h1[(k - 1) & 1])[(bg * 16 + fb) * HID + cg * 16 + fu] =
                __float2half_rn(hv);
        }

        warp_arrive(bg, sarr_addr);      // two-level: smem agg + 1 global atomic
    }
}

// ---------------- fc1: smem-staged weight tile, coalesced --------------------
__global__ void __launch_bounds__(256) fc1_kernel(
    const float* __restrict__ fc1w, const float* __restrict__ fc1b)
{
    extern __shared__ unsigned fsm[];
    float*    wsm = (float*)fsm;            // [32][516] padded
    unsigned* hsm = fsm + 32 * 516;         // [16][256] h as half2 words

    const int tid  = threadIdx.x;
    const int bgrp = blockIdx.y;
    const int jbase = blockIdx.x * 32;

    #pragma unroll
    for (int i = tid; i < 4096; i += 256)
        hsm[i] = d_h1[1][bgrp * 4096 + i];
    #pragma unroll
    for (int i = tid; i < 32 * 128; i += 256) {
        int row = i >> 7, k4 = i & 127;
        *(float4*)&wsm[row * 516 + k4 * 4] =
            *(const float4*)&fc1w[(size_t)(jbase + row) * HID + k4 * 4];
    }
    __syncthreads();

    const int j   = tid & 31;
    const int wid = tid >> 5;
    float acc0 = 0.f, acc1 = 0.f;
    const float* wr = wsm + j * 516;
    const unsigned* h0p = hsm + (wid * 2) * 256;
    const unsigned* h1p = hsm + (wid * 2 + 1) * 256;
    #pragma unroll 4
    for (int k4 = 0; k4 < 128; ++k4) {
        float4 wv = *(const float4*)&wr[k4 * 4];
        uint2 hpa = *(const uint2*)(h0p + k4 * 2);
        uint2 hpb = *(const uint2*)(h1p + k4 * 2);
        float2 a0 = __half22float2(*(__half2*)&hpa.x);
        float2 a1 = __half22float2(*(__half2*)&hpa.y);
        float2 b0 = __half22float2(*(__half2*)&hpb.x);
        float2 b1 = __half22float2(*(__half2*)&hpb.y);
        acc0 = fmaf(wv.x, a0.x, acc0); acc0 = fmaf(wv.y, a0.y, acc0);
        acc0 = fmaf(wv.z, a1.x, acc0); acc0 = fmaf(wv.w, a1.y, acc0);
        acc1 = fmaf(wv.x, b0.x, acc1); acc1 = fmaf(wv.y, b0.y, acc1);
        acc1 = fmaf(wv.z, b1.x, acc1); acc1 = fmaf(wv.w, b1.y, acc1);
    }
    float bj = fc1b[jbase + j];
    d_y1[(size_t)(bgrp * 16 + wid * 2)     * HID + jbase + j] = acc0 + bj;
    d_y1[(size_t)(bgrp * 16 + wid * 2 + 1) * HID + jbase + j] = acc1 + bj;
}

// ---------------- fc2 + relu: out[64,24] -----------------------------------------
__global__ void __launch_bounds__(192) fc2_kernel(
    const float* __restrict__ fc2w, const float* __restrict__ fc2b,
    float* __restrict__ out)
{
    __shared__ float ys[HID];
    const int b = blockIdx.x;
    const int tid = threadIdx.x;
    for (int i = tid; i < HID; i += 192) ys[i] = d_y1[(size_t)b * HID + i];
    __syncthreads();
    int j = tid >> 3, part = tid & 7;
    const float4* wr = (const float4*)(fc2w + (size_t)j * HID + part * 64);
    const float4* yv = (const float4*)(ys + part * 64);
    float a = 0.0f;
    #pragma unroll
    for (int kk = 0; kk < 16; ++kk) {
        float4 wv = wr[kk];
        float4 xv = yv[kk];
        a = fmaf(wv.x, xv.x, a);
        a = fmaf(wv.y, xv.y, a);
        a = fmaf(wv.z, xv.z, a);
        a = fmaf(wv.w, xv.w, a);
    }
    a += __shfl_down_sync(0xffffffffu, a, 4, 8);
    a += __shfl_down_sync(0xffffffffu, a, 2, 8);
    a += __shfl_down_sync(0xffffffffu, a, 1, 8);
    if (part == 0)
        out[b * OUTN + j] = fmaxf(a + fc2b[j], 0.0f);
}

// ---------------- launch ---------------------------------------------------------
extern "C" void kernel_launch(void* const* d_in, const int* in_sizes, int n_in,
                              void* d_out, int out_size)
{
    const float* x    = (const float*)d_in[0];
    const float* wf0  = (const float*)d_in[1];
    const float* bf0  = (const float*)d_in[2];
    const float* wi0  = (const float*)d_in[3];
    const float* bi0  = (const float*)d_in[4];
    const float* wo0  = (const float*)d_in[5];
    const float* bo0  = (const float*)d_in[6];
    const float* wg0  = (const float*)d_in[7];
    const float* bg0  = (const float*)d_in[8];
    const float* wf1  = (const float*)d_in[9];
    const float* bf1  = (const float*)d_in[10];
    const float* wi1  = (const float*)d_in[11];
    const float* bi1  = (const float*)d_in[12];
    const float* wo1  = (const float*)d_in[13];
    const float* bo1  = (const float*)d_in[14];
    const float* wg1  = (const float*)d_in[15];
    const float* bg1  = (const float*)d_in[16];
    const float* fc1w = (const float*)d_in[17];
    const float* fc1b = (const float*)d_in[18];
    const float* fc2w = (const float*)d_in[19];
    const float* fc2b = (const float*)d_in[20];
    float* out = (float*)d_out;

    cudaFuncSetAttribute(scan_kernel,
                         cudaFuncAttributeMaxDynamicSharedMemorySize, SMEM_BYTES);
    cudaFuncSetAttribute(xz_gemm_kernel,
                         cudaFuncAttributeMaxDynamicSharedMemorySize, XG_SMEM_BYTES);
    cudaFuncSetAttribute(fc1_kernel,
                         cudaFuncAttributeMaxDynamicSharedMemorySize, FC1_SMEM_BYTES);

    prep_kernel<<<4096, 256>>>(x, wf0, wi0, wo0, wg0, bf0, bi0, bo0, bg0,
                               wf1, wi1, wo1, wg1, bf1, bi1, bo1, bg1);
    dim3 xzgrid(256, 8);
    xz_gemm_kernel<<<xzgrid, NT, XG_SMEM_BYTES>>>();
    scan_kernel<<<NCTA, NT, SMEM_BYTES>>>();
    dim3 fc1grid(16, 4);
    fc1_kernel<<<fc1grid, 256, FC1_SMEM_BYTES>>>(fc1w, fc1b);
    fc2_kernel<<<BATCH, 192>>>(fc2w, fc2b, out);
}